// round 11
// baseline (speedup 1.0000x reference)
#include <cuda_runtime.h>
#include <cuda_bf16.h>
#include <math.h>

#define HID 1024
#define IN_SIZE 228
#define COND_SIZE 100
#define N_COND 40
#define VOCAB 32000
#define NSTEPS 512
#define FEAT 1252           // HID + IN_SIZE
#define SCAN_CTAS 64        // fewer, fatter CTAs: halves barrier participants

// ---------------- scratch (device globals; no allocation allowed) ------------
__device__ float g_de[IN_SIZE];
__device__ float g_h0[HID];
__device__ float g_gi[2 * 3 * HID];
__device__ float g_outde[VOCAB];         // de-part + out_b
__device__ float g_hs[NSTEPS * HID];     // hidden states (GEMM A, fp32 master)
__device__ unsigned int g_cnt;           // R1 barrier: monotonic counter
__device__ volatile unsigned int g_flag; // R1 barrier: monotonic release flag
// split-bf16 operands for the tensor-core GEMM
__device__ __nv_bfloat16 g_ahi[NSTEPS * HID];
__device__ __nv_bfloat16 g_alo[NSTEPS * HID];
__device__ __nv_bfloat16 g_whi[(size_t)VOCAB * HID];
__device__ __nv_bfloat16 g_wlo[(size_t)VOCAB * HID];

// ---------------- f32x2 helpers ----------------------------------------------
__device__ __forceinline__ unsigned long long pk2(float lo, float hi) {
    unsigned long long r;
    asm("mov.b64 %0, {%1,%2};" : "=l"(r) : "f"(lo), "f"(hi));
    return r;
}
__device__ __forceinline__ unsigned long long fma2(unsigned long long a,
                                                   unsigned long long b,
                                                   unsigned long long c) {
    unsigned long long d;
    asm("fma.rn.f32x2 %0, %1, %2, %3;" : "=l"(d) : "l"(a), "l"(b), "l"(c));
    return d;
}
__device__ __forceinline__ float2 upk2(unsigned long long v) {
    float2 f;
    asm("mov.b64 {%0,%1}, %2;" : "=f"(f.x), "=f"(f.y) : "l"(v));
    return f;
}

// ---------------- prep: de, h0, barrier reset --------------------------------
__global__ void prep_kernel(const float* __restrict__ z,
                            const float* __restrict__ cond,
                            const float* __restrict__ i2h_W,
                            const float* __restrict__ i2h_b,
                            const float* __restrict__ c2h_W,
                            const float* __restrict__ c2h_b) {
    __shared__ float sde[IN_SIZE];
    int tid = threadIdx.x;
    if (tid < 128) sde[tid] = z[tid];
    if (tid < COND_SIZE) {
        float acc = c2h_b[tid];
#pragma unroll
        for (int k = 0; k < N_COND; k++) acc += cond[k] * c2h_W[tid * N_COND + k];
        sde[128 + tid] = acc;
    }
    if (tid == 0) { g_cnt = 0; g_flag = 0; }
    __syncthreads();
    if (tid < IN_SIZE) g_de[tid] = sde[tid];
    for (int r = tid; r < HID; r += blockDim.x) {
        float acc = i2h_b[r];
        const float* w = i2h_W + (size_t)r * IN_SIZE;
#pragma unroll 4
        for (int k = 0; k < IN_SIZE; k++) acc += sde[k] * w[k];
        g_h0[r] = acc;
    }
}

// ---------------- gi: the 2 distinct input-gate rows -------------------------
__global__ void gi_kernel(const float* __restrict__ embed_W,
                          const float* __restrict__ W_ih,
                          const float* __restrict__ b_ih,
                          const float* __restrict__ b_hh) {
    __shared__ float xs[2][FEAT];
    int tid = threadIdx.x;
    for (int i = tid; i < HID; i += blockDim.x) {
        xs[0][i] = fmaxf(embed_W[1 * HID + i], 0.f);  // SOS = 1
        xs[1][i] = fmaxf(embed_W[2 * HID + i], 0.f);  // UNK = 2
    }
    for (int i = tid; i < IN_SIZE; i += blockDim.x) {
        float d = g_de[i];
        xs[0][HID + i] = d;
        xs[1][HID + i] = d;
    }
    __syncthreads();
    int lane = tid & 31;
    int warp = (blockIdx.x * blockDim.x + tid) >> 5;
    int nwarp = (gridDim.x * blockDim.x) >> 5;
    for (int task = warp; task < 2 * 3 * HID; task += nwarp) {
        int v = task >= 3 * HID;
        int row = task - v * 3 * HID;
        const float* w = W_ih + (size_t)row * FEAT;
        const float* x = xs[v];
        float acc = 0.f;
        for (int k = lane; k < FEAT; k += 32) acc += w[k] * x[k];
#pragma unroll
        for (int o = 16; o > 0; o >>= 1) acc += __shfl_xor_sync(0xffffffffu, acc, o);
        if (lane == 0) {
            float val = acc + b_ih[row];
            if (row < 2 * HID) val += b_hh[row];
            g_gi[task] = val;
        }
    }
}

// ---------------- outde: broadcast term of the output ------------------------
__global__ void outde_kernel(const float* __restrict__ out_W,
                             const float* __restrict__ out_b) {
    __shared__ float sde[IN_SIZE];
    int tid = threadIdx.x;
    if (tid < IN_SIZE) sde[tid] = g_de[tid];
    __syncthreads();
    int v = blockIdx.x * blockDim.x + tid;
    if (v < VOCAB) {
        const float* w = out_W + (size_t)v * FEAT + HID;
        float acc = out_b[v];
#pragma unroll 4
        for (int k = 0; k < IN_SIZE; k++) acc += sde[k] * w[k];
        g_outde[v] = acc;
    }
}

// ---------------- W conversion: out_W[:, :1024] -> hi/lo bf16 ----------------
__global__ void wconv_kernel(const float* __restrict__ out_W) {
    size_t i8 = (size_t)blockIdx.x * blockDim.x + threadIdx.x;
    if (i8 >= (size_t)VOCAB * HID / 8) return;
    int r = (int)(i8 >> 7);
    int c8 = (int)(i8 & 127);
    const float4* src = (const float4*)(out_W + (size_t)r * FEAT + c8 * 8);
    float4 v0 = src[0], v1 = src[1];
    float v[8] = { v0.x, v0.y, v0.z, v0.w, v1.x, v1.y, v1.z, v1.w };
    unsigned hu[4], lu[4];
#pragma unroll
    for (int p = 0; p < 4; p++) {
        __nv_bfloat16 h0 = __float2bfloat16(v[2 * p]);
        __nv_bfloat16 h1 = __float2bfloat16(v[2 * p + 1]);
        __nv_bfloat16 l0 = __float2bfloat16(v[2 * p] - __bfloat162float(h0));
        __nv_bfloat16 l1 = __float2bfloat16(v[2 * p + 1] - __bfloat162float(h1));
        hu[p] = (unsigned)__bfloat16_as_ushort(h0) | ((unsigned)__bfloat16_as_ushort(h1) << 16);
        lu[p] = (unsigned)__bfloat16_as_ushort(l0) | ((unsigned)__bfloat16_as_ushort(l1) << 16);
    }
    *(uint4*)(g_whi + i8 * 8) = make_uint4(hu[0], hu[1], hu[2], hu[3]);
    *(uint4*)(g_wlo + i8 * 8) = make_uint4(lu[0], lu[1], lu[2], lu[3]);
}

// ---------------- A conversion: g_hs -> hi/lo bf16 ---------------------------
__global__ void aconv_kernel() {
    size_t i8 = (size_t)blockIdx.x * blockDim.x + threadIdx.x;
    if (i8 >= (size_t)NSTEPS * HID / 8) return;
    const float4* src = (const float4*)(g_hs + i8 * 8);
    float4 v0 = src[0], v1 = src[1];
    float v[8] = { v0.x, v0.y, v0.z, v0.w, v1.x, v1.y, v1.z, v1.w };
    unsigned hu[4], lu[4];
#pragma unroll
    for (int p = 0; p < 4; p++) {
        __nv_bfloat16 h0 = __float2bfloat16(v[2 * p]);
        __nv_bfloat16 h1 = __float2bfloat16(v[2 * p + 1]);
        __nv_bfloat16 l0 = __float2bfloat16(v[2 * p] - __bfloat162float(h0));
        __nv_bfloat16 l1 = __float2bfloat16(v[2 * p + 1] - __bfloat162float(h1));
        hu[p] = (unsigned)__bfloat16_as_ushort(h0) | ((unsigned)__bfloat16_as_ushort(h1) << 16);
        lu[p] = (unsigned)__bfloat16_as_ushort(l0) | ((unsigned)__bfloat16_as_ushort(l1) << 16);
    }
    *(uint4*)(g_ahi + i8 * 8) = make_uint4(hu[0], hu[1], hu[2], hu[3]);
    *(uint4*)(g_alo + i8 * 8) = make_uint4(lu[0], lu[1], lu[2], lu[3]);
}

// ---------------- scan: 64 CTAs x 512 threads, R1-EXACT barrier --------------
// 16 compute warps per CTA; warp w owns hidden index j = bid*16 + w.
// W_hh rows {j, H+j, 2H+j} in 48 packed f32x2 regs per lane (unchanged).
// Halving CTA count halves the same-address atomic serialization per step
// (the measured dominant barrier term).
__global__ void __launch_bounds__(512) scan_kernel(const float* __restrict__ W_hh,
                                                   const float* __restrict__ b_hh) {
    __shared__ float sh[HID];
    int tid = threadIdx.x;
    int lane = tid & 31;
    int w = tid >> 5;
    int j = blockIdx.x * 16 + w;

    const float* Wr = W_hh + (size_t)j * HID;
    const float* Wu = W_hh + (size_t)(HID + j) * HID;
    const float* Wn = W_hh + (size_t)(2 * HID + j) * HID;

    unsigned long long wr2[16], wu2[16], wn2[16];
#pragma unroll
    for (int k = 0; k < 16; k++) {
        float2 a = *(const float2*)(Wr + 64 * k + 2 * lane); wr2[k] = pk2(a.x, a.y);
        float2 b = *(const float2*)(Wu + 64 * k + 2 * lane); wu2[k] = pk2(b.x, b.y);
        float2 c = *(const float2*)(Wn + 64 * k + 2 * lane); wn2[k] = pk2(c.x, c.y);
    }
    float gi_r0 = g_gi[j],           gi_u0 = g_gi[HID + j],     gi_n0 = g_gi[2 * HID + j];
    float gi_r1 = g_gi[3 * HID + j], gi_u1 = g_gi[4 * HID + j], gi_n1 = g_gi[5 * HID + j];
    float bhn = b_hh[2 * HID + j];
    const unsigned nCTA = gridDim.x;

    for (int t = 0; t < NSTEPS; t++) {
        // stage current h into smem (256 float4 = 1024 floats; threads 0-255)
        if (tid < 256) {
            const float4* src = (const float4*)((t == 0) ? g_h0 : (g_hs + (size_t)(t - 1) * HID));
            ((float4*)sh)[tid] = __ldcg(src + tid);
        }
        __syncthreads();

        unsigned long long ar2 = 0ull, au2 = 0ull, an2 = 0ull;
#pragma unroll
        for (int k = 0; k < 16; k++) {
            float2 h2 = *(const float2*)&sh[64 * k + 2 * lane];
            unsigned long long hp = pk2(h2.x, h2.y);
            ar2 = fma2(wr2[k], hp, ar2);
            au2 = fma2(wu2[k], hp, au2);
            an2 = fma2(wn2[k], hp, an2);
        }
        float2 fr = upk2(ar2), fu = upk2(au2), fn = upk2(an2);
        float ar = fr.x + fr.y, au = fu.x + fu.y, an = fn.x + fn.y;
#pragma unroll
        for (int o = 16; o > 0; o >>= 1) {
            ar += __shfl_xor_sync(0xffffffffu, ar, o);
            au += __shfl_xor_sync(0xffffffffu, au, o);
            an += __shfl_xor_sync(0xffffffffu, an, o);
        }
        if (lane == 0) {
            float gr = (t == 0) ? gi_r0 : gi_r1;
            float gu = (t == 0) ? gi_u0 : gi_u1;
            float gn = (t == 0) ? gi_n0 : gi_n1;
            float r = 1.f / (1.f + __expf(-(gr + ar)));
            float u = 1.f / (1.f + __expf(-(gu + au)));
            float narg = gn + r * (an + bhn);
            float n = 1.f - 2.f / (__expf(2.f * narg) + 1.f);
            float hnew = (1.f - u) * n + u * sh[j];
            __stcg(g_hs + (size_t)t * HID + j, hnew);
        }
        __threadfence();
        __syncthreads();
        if (tid == 0) {
            unsigned target = nCTA * (unsigned)(t + 1);
            unsigned old = atomicAdd(&g_cnt, 1u);
            if (old == target - 1u) {
                g_flag = (unsigned)(t + 1);           // release
            } else {
                while (g_flag < (unsigned)(t + 1)) {} // spin (measured benign)
            }
            __threadfence();
        }
        __syncthreads();
    }
}

// ---------------- tensor-core GEMM: split-bf16, mma.sync m16n8k16 ------------
#define MMA_OP(d, a, b)                                                        \
    asm("mma.sync.aligned.m16n8k16.row.col.f32.bf16.bf16.f32 "                 \
        "{%0,%1,%2,%3}, {%4,%5,%6,%7}, {%8,%9}, {%0,%1,%2,%3};"                \
        : "+f"(d[0]), "+f"(d[1]), "+f"(d[2]), "+f"(d[3])                        \
        : "r"(a[0]), "r"(a[1]), "r"(a[2]), "r"(a[3]), "r"(b[0]), "r"(b[1]))

#define KPAD 40

__global__ void __launch_bounds__(256) mma_gemm_kernel(float* __restrict__ out) {
    __shared__ __nv_bfloat16 As[2][128][KPAD];
    __shared__ __nv_bfloat16 Bs[2][128][KPAD];
    int tid = threadIdx.x;
    int lane = tid & 31, wid = tid >> 5;
    int wm = wid & 1, wn = wid >> 1;
    int g = lane >> 2, tig = lane & 3;
    int tn = blockIdx.x * 128, tm = blockIdx.y * 128;

    float acc[4][4][4];
#pragma unroll
    for (int mi = 0; mi < 4; mi++)
#pragma unroll
        for (int ni = 0; ni < 4; ni++)
#pragma unroll
            for (int p = 0; p < 4; p++) acc[mi][ni][p] = 0.f;

    for (int k0 = 0; k0 < HID; k0 += 32) {
        __syncthreads();
        {
            int j = tid << 1;
#pragma unroll
            for (int s = 0; s < 2; s++) {
                int jj = j + s;
                int r = jj >> 2, q = jj & 3;
                const uint4* sa_h = (const uint4*)(g_ahi + (size_t)(tm + r) * HID + k0);
                const uint4* sa_l = (const uint4*)(g_alo + (size_t)(tm + r) * HID + k0);
                const uint4* sb_h = (const uint4*)(g_whi + (size_t)(tn + r) * HID + k0);
                const uint4* sb_l = (const uint4*)(g_wlo + (size_t)(tn + r) * HID + k0);
                *(uint4*)&As[0][r][q * 8] = sa_h[q];
                *(uint4*)&As[1][r][q * 8] = sa_l[q];
                *(uint4*)&Bs[0][r][q * 8] = sb_h[q];
                *(uint4*)&Bs[1][r][q * 8] = sb_l[q];
            }
        }
        __syncthreads();

#pragma unroll
        for (int ks = 0; ks < 2; ks++) {
            int kk = ks * 16 + 2 * tig;
            unsigned bh[4][2], bl[4][2];
#pragma unroll
            for (int ni = 0; ni < 4; ni++) {
                int rn = wn * 32 + ni * 8 + g;
                bh[ni][0] = *(const unsigned*)&Bs[0][rn][kk];
                bh[ni][1] = *(const unsigned*)&Bs[0][rn][kk + 8];
                bl[ni][0] = *(const unsigned*)&Bs[1][rn][kk];
                bl[ni][1] = *(const unsigned*)&Bs[1][rn][kk + 8];
            }
#pragma unroll
            for (int mi = 0; mi < 4; mi++) {
                int rm = wm * 64 + mi * 16 + g;
                unsigned ah[4], al[4];
                ah[0] = *(const unsigned*)&As[0][rm][kk];
                ah[1] = *(const unsigned*)&As[0][rm + 8][kk];
                ah[2] = *(const unsigned*)&As[0][rm][kk + 8];
                ah[3] = *(const unsigned*)&As[0][rm + 8][kk + 8];
                al[0] = *(const unsigned*)&As[1][rm][kk];
                al[1] = *(const unsigned*)&As[1][rm + 8][kk];
                al[2] = *(const unsigned*)&As[1][rm][kk + 8];
                al[3] = *(const unsigned*)&As[1][rm + 8][kk + 8];
#pragma unroll
                for (int ni = 0; ni < 4; ni++) {
                    MMA_OP(acc[mi][ni], ah, bh[ni]);
                    MMA_OP(acc[mi][ni], ah, bl[ni]);
                    MMA_OP(acc[mi][ni], al, bh[ni]);
                }
            }
        }
    }

#pragma unroll
    for (int mi = 0; mi < 4; mi++) {
#pragma unroll
        for (int ni = 0; ni < 4; ni++) {
            int row = tm + wm * 64 + mi * 16 + g;
            int col = tn + wn * 32 + ni * 8 + 2 * tig;
            float o0 = g_outde[col], o1 = g_outde[col + 1];
            float2 r0 = { acc[mi][ni][0] + o0, acc[mi][ni][1] + o1 };
            float2 r1 = { acc[mi][ni][2] + o0, acc[mi][ni][3] + o1 };
            *(float2*)(out + (size_t)row * VOCAB + col) = r0;
            *(float2*)(out + (size_t)(row + 8) * VOCAB + col) = r1;
        }
    }
}

// ---------------- entry ------------------------------------------------------
extern "C" void kernel_launch(void* const* d_in, const int* in_sizes, int n_in,
                              void* d_out, int out_size) {
    const float* z      = (const float*)d_in[0];
    const float* cond   = (const float*)d_in[1];
    // d_in[2] = inputs (unused: word_dropout=1.0), d_in[3] = temperature (unused)
    const float* embedW = (const float*)d_in[4];
    const float* W_ih   = (const float*)d_in[5];
    const float* W_hh   = (const float*)d_in[6];
    const float* b_ih   = (const float*)d_in[7];
    const float* b_hh   = (const float*)d_in[8];
    const float* i2h_W  = (const float*)d_in[9];
    const float* i2h_b  = (const float*)d_in[10];
    const float* c2h_W  = (const float*)d_in[11];
    const float* c2h_b  = (const float*)d_in[12];
    const float* out_W  = (const float*)d_in[13];
    const float* out_b  = (const float*)d_in[14];
    float* out = (float*)d_out;

    prep_kernel<<<1, 256>>>(z, cond, i2h_W, i2h_b, c2h_W, c2h_b);
    gi_kernel<<<96, 256>>>(embedW, W_ih, b_ih, b_hh);
    outde_kernel<<<(VOCAB + 255) / 256, 256>>>(out_W, out_b);
    wconv_kernel<<<(VOCAB * (HID / 8) + 255) / 256, 256>>>(out_W);
    scan_kernel<<<SCAN_CTAS, 512>>>(W_hh, b_hh);
    aconv_kernel<<<(NSTEPS * (HID / 8) + 255) / 256, 256>>>();
    mma_gemm_kernel<<<dim3(VOCAB / 128, NSTEPS / 128), 256>>>(out);
}

// round 12
// speedup vs baseline: 1.1749x; 1.1749x over previous
#include <cuda_runtime.h>
#include <cuda_bf16.h>
#include <math.h>

#define HID 1024
#define IN_SIZE 228
#define COND_SIZE 100
#define N_COND 40
#define VOCAB 32000
#define NSTEPS 512
#define FEAT 1252           // HID + IN_SIZE
#define SCAN_CTAS 128

// ---------------- scratch (device globals; no allocation allowed) ------------
__device__ float g_de[IN_SIZE];
__device__ float g_h0[HID];
__device__ float g_gi[2 * 3 * HID];
__device__ float g_outde[VOCAB];         // de-part + out_b
__device__ float g_hs[NSTEPS * HID];     // hidden states (GEMM A, fp32 master)
__device__ unsigned int g_cnt;           // R1 barrier: monotonic counter
__device__ volatile unsigned int g_flag; // R1 barrier: monotonic release flag
// split-bf16 operands for the tensor-core GEMM
__device__ __nv_bfloat16 g_ahi[NSTEPS * HID];
__device__ __nv_bfloat16 g_alo[NSTEPS * HID];
__device__ __nv_bfloat16 g_whi[(size_t)VOCAB * HID];
__device__ __nv_bfloat16 g_wlo[(size_t)VOCAB * HID];

// ---------------- f32x2 helpers ----------------------------------------------
__device__ __forceinline__ unsigned long long pk2(float lo, float hi) {
    unsigned long long r;
    asm("mov.b64 %0, {%1,%2};" : "=l"(r) : "f"(lo), "f"(hi));
    return r;
}
__device__ __forceinline__ unsigned long long fma2(unsigned long long a,
                                                   unsigned long long b,
                                                   unsigned long long c) {
    unsigned long long d;
    asm("fma.rn.f32x2 %0, %1, %2, %3;" : "=l"(d) : "l"(a), "l"(b), "l"(c));
    return d;
}
__device__ __forceinline__ float2 upk2(unsigned long long v) {
    float2 f;
    asm("mov.b64 {%0,%1}, %2;" : "=f"(f.x), "=f"(f.y) : "l"(v));
    return f;
}

// ---------------- prep: de, h0, barrier reset --------------------------------
__global__ void prep_kernel(const float* __restrict__ z,
                            const float* __restrict__ cond,
                            const float* __restrict__ i2h_W,
                            const float* __restrict__ i2h_b,
                            const float* __restrict__ c2h_W,
                            const float* __restrict__ c2h_b) {
    __shared__ float sde[IN_SIZE];
    int tid = threadIdx.x;
    if (tid < 128) sde[tid] = z[tid];
    if (tid < COND_SIZE) {
        float acc = c2h_b[tid];
#pragma unroll
        for (int k = 0; k < N_COND; k++) acc += cond[k] * c2h_W[tid * N_COND + k];
        sde[128 + tid] = acc;
    }
    if (tid == 0) { g_cnt = 0; g_flag = 0; }
    __syncthreads();
    if (tid < IN_SIZE) g_de[tid] = sde[tid];
    for (int r = tid; r < HID; r += blockDim.x) {
        float acc = i2h_b[r];
        const float* w = i2h_W + (size_t)r * IN_SIZE;
#pragma unroll 4
        for (int k = 0; k < IN_SIZE; k++) acc += sde[k] * w[k];
        g_h0[r] = acc;
    }
}

// ---------------- gi: the 2 distinct input-gate rows -------------------------
__global__ void gi_kernel(const float* __restrict__ embed_W,
                          const float* __restrict__ W_ih,
                          const float* __restrict__ b_ih,
                          const float* __restrict__ b_hh) {
    __shared__ float xs[2][FEAT];
    int tid = threadIdx.x;
    for (int i = tid; i < HID; i += blockDim.x) {
        xs[0][i] = fmaxf(embed_W[1 * HID + i], 0.f);  // SOS = 1
        xs[1][i] = fmaxf(embed_W[2 * HID + i], 0.f);  // UNK = 2
    }
    for (int i = tid; i < IN_SIZE; i += blockDim.x) {
        float d = g_de[i];
        xs[0][HID + i] = d;
        xs[1][HID + i] = d;
    }
    __syncthreads();
    int lane = tid & 31;
    int warp = (blockIdx.x * blockDim.x + tid) >> 5;
    int nwarp = (gridDim.x * blockDim.x) >> 5;
    for (int task = warp; task < 2 * 3 * HID; task += nwarp) {
        int v = task >= 3 * HID;
        int row = task - v * 3 * HID;
        const float* w = W_ih + (size_t)row * FEAT;
        const float* x = xs[v];
        float acc = 0.f;
        for (int k = lane; k < FEAT; k += 32) acc += w[k] * x[k];
#pragma unroll
        for (int o = 16; o > 0; o >>= 1) acc += __shfl_xor_sync(0xffffffffu, acc, o);
        if (lane == 0) {
            float val = acc + b_ih[row];
            if (row < 2 * HID) val += b_hh[row];
            g_gi[task] = val;
        }
    }
}

// ---------------- outde: broadcast term of the output ------------------------
__global__ void outde_kernel(const float* __restrict__ out_W,
                             const float* __restrict__ out_b) {
    __shared__ float sde[IN_SIZE];
    int tid = threadIdx.x;
    if (tid < IN_SIZE) sde[tid] = g_de[tid];
    __syncthreads();
    int v = blockIdx.x * blockDim.x + tid;
    if (v < VOCAB) {
        const float* w = out_W + (size_t)v * FEAT + HID;
        float acc = out_b[v];
#pragma unroll 4
        for (int k = 0; k < IN_SIZE; k++) acc += sde[k] * w[k];
        g_outde[v] = acc;
    }
}

// ---------------- W conversion: out_W[:, :1024] -> hi/lo bf16 ----------------
__global__ void wconv_kernel(const float* __restrict__ out_W) {
    size_t i8 = (size_t)blockIdx.x * blockDim.x + threadIdx.x;
    if (i8 >= (size_t)VOCAB * HID / 8) return;
    int r = (int)(i8 >> 7);
    int c8 = (int)(i8 & 127);
    const float4* src = (const float4*)(out_W + (size_t)r * FEAT + c8 * 8);
    float4 v0 = src[0], v1 = src[1];
    float v[8] = { v0.x, v0.y, v0.z, v0.w, v1.x, v1.y, v1.z, v1.w };
    unsigned hu[4], lu[4];
#pragma unroll
    for (int p = 0; p < 4; p++) {
        __nv_bfloat16 h0 = __float2bfloat16(v[2 * p]);
        __nv_bfloat16 h1 = __float2bfloat16(v[2 * p + 1]);
        __nv_bfloat16 l0 = __float2bfloat16(v[2 * p] - __bfloat162float(h0));
        __nv_bfloat16 l1 = __float2bfloat16(v[2 * p + 1] - __bfloat162float(h1));
        hu[p] = (unsigned)__bfloat16_as_ushort(h0) | ((unsigned)__bfloat16_as_ushort(h1) << 16);
        lu[p] = (unsigned)__bfloat16_as_ushort(l0) | ((unsigned)__bfloat16_as_ushort(l1) << 16);
    }
    *(uint4*)(g_whi + i8 * 8) = make_uint4(hu[0], hu[1], hu[2], hu[3]);
    *(uint4*)(g_wlo + i8 * 8) = make_uint4(lu[0], lu[1], lu[2], lu[3]);
}

// ---------------- A conversion: g_hs -> hi/lo bf16 ---------------------------
__global__ void aconv_kernel() {
    size_t i8 = (size_t)blockIdx.x * blockDim.x + threadIdx.x;
    if (i8 >= (size_t)NSTEPS * HID / 8) return;
    const float4* src = (const float4*)(g_hs + i8 * 8);
    float4 v0 = src[0], v1 = src[1];
    float v[8] = { v0.x, v0.y, v0.z, v0.w, v1.x, v1.y, v1.z, v1.w };
    unsigned hu[4], lu[4];
#pragma unroll
    for (int p = 0; p < 4; p++) {
        __nv_bfloat16 h0 = __float2bfloat16(v[2 * p]);
        __nv_bfloat16 h1 = __float2bfloat16(v[2 * p + 1]);
        __nv_bfloat16 l0 = __float2bfloat16(v[2 * p] - __bfloat162float(h0));
        __nv_bfloat16 l1 = __float2bfloat16(v[2 * p + 1] - __bfloat162float(h1));
        hu[p] = (unsigned)__bfloat16_as_ushort(h0) | ((unsigned)__bfloat16_as_ushort(h1) << 16);
        lu[p] = (unsigned)__bfloat16_as_ushort(l0) | ((unsigned)__bfloat16_as_ushort(l1) << 16);
    }
    *(uint4*)(g_ahi + i8 * 8) = make_uint4(hu[0], hu[1], hu[2], hu[3]);
    *(uint4*)(g_alo + i8 * 8) = make_uint4(lu[0], lu[1], lu[2], lu[3]);
}

// ---------------- scan: R8-EXACT (measured best 1203us; FROZEN) --------------
__global__ void __launch_bounds__(256) scan_kernel(const float* __restrict__ W_hh,
                                                   const float* __restrict__ b_hh) {
    __shared__ float sh[HID];
    int tid = threadIdx.x;
    int lane = tid & 31;
    int w = tid >> 5;
    int j = blockIdx.x * 8 + w;

    const float* Wr = W_hh + (size_t)j * HID;
    const float* Wu = W_hh + (size_t)(HID + j) * HID;
    const float* Wn = W_hh + (size_t)(2 * HID + j) * HID;

    unsigned long long wr2[16], wu2[16], wn2[16];
#pragma unroll
    for (int k = 0; k < 16; k++) {
        float2 a = *(const float2*)(Wr + 64 * k + 2 * lane); wr2[k] = pk2(a.x, a.y);
        float2 b = *(const float2*)(Wu + 64 * k + 2 * lane); wu2[k] = pk2(b.x, b.y);
        float2 c = *(const float2*)(Wn + 64 * k + 2 * lane); wn2[k] = pk2(c.x, c.y);
    }
    float gi_r0 = g_gi[j],           gi_u0 = g_gi[HID + j],     gi_n0 = g_gi[2 * HID + j];
    float gi_r1 = g_gi[3 * HID + j], gi_u1 = g_gi[4 * HID + j], gi_n1 = g_gi[5 * HID + j];
    float bhn = b_hh[2 * HID + j];
    const unsigned nCTA = gridDim.x;

    for (int t = 0; t < NSTEPS; t++) {
        const float4* src = (const float4*)((t == 0) ? g_h0 : (g_hs + (size_t)(t - 1) * HID));
        ((float4*)sh)[tid] = __ldcg(src + tid);
        __syncthreads();

        unsigned long long ar2 = 0ull, au2 = 0ull, an2 = 0ull;
#pragma unroll
        for (int k = 0; k < 16; k++) {
            float2 h2 = *(const float2*)&sh[64 * k + 2 * lane];
            unsigned long long hp = pk2(h2.x, h2.y);
            ar2 = fma2(wr2[k], hp, ar2);
            au2 = fma2(wu2[k], hp, au2);
            an2 = fma2(wn2[k], hp, an2);
        }
        float2 fr = upk2(ar2), fu = upk2(au2), fn = upk2(an2);
        float ar = fr.x + fr.y, au = fu.x + fu.y, an = fn.x + fn.y;
#pragma unroll
        for (int o = 16; o > 0; o >>= 1) {
            ar += __shfl_xor_sync(0xffffffffu, ar, o);
            au += __shfl_xor_sync(0xffffffffu, au, o);
            an += __shfl_xor_sync(0xffffffffu, an, o);
        }
        if (lane == 0) {
            float gr = (t == 0) ? gi_r0 : gi_r1;
            float gu = (t == 0) ? gi_u0 : gi_u1;
            float gn = (t == 0) ? gi_n0 : gi_n1;
            float r = 1.f / (1.f + __expf(-(gr + ar)));
            float u = 1.f / (1.f + __expf(-(gu + au)));
            float narg = gn + r * (an + bhn);
            float n = 1.f - 2.f / (__expf(2.f * narg) + 1.f);
            float hnew = (1.f - u) * n + u * sh[j];
            __stcg(g_hs + (size_t)t * HID + j, hnew);
        }
        __threadfence();
        __syncthreads();
        if (tid == 0) {
            unsigned target = nCTA * (unsigned)(t + 1);
            unsigned old = atomicAdd(&g_cnt, 1u);
            if (old == target - 1u) {
                g_flag = (unsigned)(t + 1);
            } else {
                while (g_flag < (unsigned)(t + 1)) {}
            }
            __threadfence();
        }
        __syncthreads();
    }
}

// ---------------- tensor-core GEMM v2: cp.async 2-stage + ldmatrix -----------
// C[512,32000] = (Ahi+Alo)(Whi+Wlo)^T + outde, dropping lo*lo.
// CTA 128x128xK32; 8 warps as 2(M)x4(N); warp tile 64x32.
// Fragment<->smem mapping identical to R8's experimentally-verified scalar loads.
#define MMA_OP(d, a, b)                                                        \
    asm("mma.sync.aligned.m16n8k16.row.col.f32.bf16.bf16.f32 "                 \
        "{%0,%1,%2,%3}, {%4,%5,%6,%7}, {%8,%9}, {%0,%1,%2,%3};"                \
        : "+f"(d[0]), "+f"(d[1]), "+f"(d[2]), "+f"(d[3])                        \
        : "r"(a[0]), "r"(a[1]), "r"(a[2]), "r"(a[3]), "r"(b[0]), "r"(b[1]))

#define LDSM_X4(r, addr)                                                       \
    asm volatile("ldmatrix.sync.aligned.m8n8.x4.shared.b16 {%0,%1,%2,%3}, [%4];" \
                 : "=r"((r)[0]), "=r"((r)[1]), "=r"((r)[2]), "=r"((r)[3])       \
                 : "r"(addr))

#define CP_ASYNC16(smem_u32, gptr)                                             \
    asm volatile("cp.async.cg.shared.global [%0], [%1], 16;"                   \
                 :: "r"(smem_u32), "l"(gptr))
#define CP_COMMIT()  asm volatile("cp.async.commit_group;")
#define CP_WAIT(n)   asm volatile("cp.async.wait_group %0;" :: "n"(n))

#define KPAD 40
#define TILE_H (128 * KPAD)          // halves per tile
#define STAGE_H (4 * TILE_H)         // Ahi, Alo, Bhi, Blo
#define GEMM_SMEM_BYTES (2 * STAGE_H * 2)

__device__ __forceinline__ unsigned smem_u32(const void* p) {
    return (unsigned)__cvta_generic_to_shared(p);
}

__global__ void __launch_bounds__(256) mma_gemm_kernel(float* __restrict__ out) {
    extern __shared__ __nv_bfloat16 smem[];
    int tid = threadIdx.x;
    int lane = tid & 31, wid = tid >> 5;
    int wm = wid & 1, wn = wid >> 1;
    int g = lane >> 2, tig = lane & 3;
    int tn = blockIdx.x * 128, tm = blockIdx.y * 128;
    int trow = lane & 7, tsel = lane >> 3;

    float acc[4][4][4];
#pragma unroll
    for (int mi = 0; mi < 4; mi++)
#pragma unroll
        for (int ni = 0; ni < 4; ni++)
#pragma unroll
            for (int p = 0; p < 4; p++) acc[mi][ni][p] = 0.f;

    // per-thread load jobs: 2 (row,q) pairs covering 128 rows x 4 q per tile
    int j0 = tid * 2;
    int r0_ = j0 >> 2, q0_ = j0 & 3;
    int r1_ = (j0 + 1) >> 2, q1_ = (j0 + 1) & 3;

    auto prefetch = [&](int k0, int st) {
        __nv_bfloat16* base = smem + st * STAGE_H;
        const __nv_bfloat16* srcs[4] = {
            g_ahi + (size_t)(tm + 0) * HID, g_alo + (size_t)(tm + 0) * HID,
            g_whi + (size_t)(tn + 0) * HID, g_wlo + (size_t)(tn + 0) * HID };
#pragma unroll
        for (int w4 = 0; w4 < 4; w4++) {
            const __nv_bfloat16* s = srcs[w4] + k0;
            __nv_bfloat16* d = base + w4 * TILE_H;
            CP_ASYNC16(smem_u32(d + r0_ * KPAD + q0_ * 8), s + (size_t)r0_ * HID + q0_ * 8);
            CP_ASYNC16(smem_u32(d + r1_ * KPAD + q1_ * 8), s + (size_t)r1_ * HID + q1_ * 8);
        }
    };

    prefetch(0, 0);
    CP_COMMIT();

    for (int it = 0; it < 32; it++) {
        int cur = it & 1;
        if (it < 31) { prefetch((it + 1) * 32, cur ^ 1); CP_COMMIT(); }
        if (it < 31) { CP_WAIT(1); } else { CP_WAIT(0); }
        __syncthreads();

        __nv_bfloat16* Ah = smem + cur * STAGE_H;
        __nv_bfloat16* Al = Ah + TILE_H;
        __nv_bfloat16* Bh = Al + TILE_H;
        __nv_bfloat16* Bl = Bh + TILE_H;

#pragma unroll
        for (int ks = 0; ks < 2; ks++) {
            int kk0 = ks * 16;
            // B fragments: one x4 covers 2 n-blocks (verified tile order)
            unsigned bh[4][2], bl[4][2];
#pragma unroll
            for (int p = 0; p < 2; p++) {
                int rn0 = wn * 32 + p * 16;
                int brow = rn0 + (tsel >> 1) * 8 + trow;
                int bk = kk0 + (tsel & 1) * 8;
                unsigned rh[4], rl[4];
                LDSM_X4(rh, smem_u32(Bh + brow * KPAD + bk));
                LDSM_X4(rl, smem_u32(Bl + brow * KPAD + bk));
                bh[2 * p][0] = rh[0]; bh[2 * p][1] = rh[1];
                bh[2 * p + 1][0] = rh[2]; bh[2 * p + 1][1] = rh[3];
                bl[2 * p][0] = rl[0]; bl[2 * p][1] = rl[1];
                bl[2 * p + 1][0] = rl[2]; bl[2 * p + 1][1] = rl[3];
            }
#pragma unroll
            for (int mi = 0; mi < 4; mi++) {
                int rm0 = wm * 64 + mi * 16;
                int arow = rm0 + (tsel & 1) * 8 + trow;
                int ak = kk0 + (tsel >> 1) * 8;
                unsigned ah[4], al[4];
                LDSM_X4(ah, smem_u32(Ah + arow * KPAD + ak));
                LDSM_X4(al, smem_u32(Al + arow * KPAD + ak));
#pragma unroll
                for (int ni = 0; ni < 4; ni++) {
                    MMA_OP(acc[mi][ni], ah, bh[ni]);
                    MMA_OP(acc[mi][ni], ah, bl[ni]);
                    MMA_OP(acc[mi][ni], al, bh[ni]);
                }
            }
        }
        __syncthreads();
    }

#pragma unroll
    for (int mi = 0; mi < 4; mi++) {
#pragma unroll
        for (int ni = 0; ni < 4; ni++) {
            int row = tm + wm * 64 + mi * 16 + g;
            int col = tn + wn * 32 + ni * 8 + 2 * tig;
            float o0 = g_outde[col], o1 = g_outde[col + 1];
            float2 r0 = { acc[mi][ni][0] + o0, acc[mi][ni][1] + o1 };
            float2 r1 = { acc[mi][ni][2] + o0, acc[mi][ni][3] + o1 };
            *(float2*)(out + (size_t)row * VOCAB + col) = r0;
            *(float2*)(out + (size_t)(row + 8) * VOCAB + col) = r1;
        }
    }
}

// ---------------- entry ------------------------------------------------------
extern "C" void kernel_launch(void* const* d_in, const int* in_sizes, int n_in,
                              void* d_out, int out_size) {
    const float* z      = (const float*)d_in[0];
    const float* cond   = (const float*)d_in[1];
    // d_in[2] = inputs (unused: word_dropout=1.0), d_in[3] = temperature (unused)
    const float* embedW = (const float*)d_in[4];
    const float* W_ih   = (const float*)d_in[5];
    const float* W_hh   = (const float*)d_in[6];
    const float* b_ih   = (const float*)d_in[7];
    const float* b_hh   = (const float*)d_in[8];
    const float* i2h_W  = (const float*)d_in[9];
    const float* i2h_b  = (const float*)d_in[10];
    const float* c2h_W  = (const float*)d_in[11];
    const float* c2h_b  = (const float*)d_in[12];
    const float* out_W  = (const float*)d_in[13];
    const float* out_b  = (const float*)d_in[14];
    float* out = (float*)d_out;

    cudaFuncSetAttribute(mma_gemm_kernel,
                         cudaFuncAttributeMaxDynamicSharedMemorySize,
                         GEMM_SMEM_BYTES);

    prep_kernel<<<1, 256>>>(z, cond, i2h_W, i2h_b, c2h_W, c2h_b);
    gi_kernel<<<96, 256>>>(embedW, W_ih, b_ih, b_hh);
    outde_kernel<<<(VOCAB + 255) / 256, 256>>>(out_W, out_b);
    wconv_kernel<<<(VOCAB * (HID / 8) + 255) / 256, 256>>>(out_W);
    scan_kernel<<<SCAN_CTAS, 256>>>(W_hh, b_hh);
    aconv_kernel<<<(NSTEPS * (HID / 8) + 255) / 256, 256>>>();
    mma_gemm_kernel<<<dim3(VOCAB / 128, NSTEPS / 128), 256, GEMM_SMEM_BYTES>>>(out);
}

// round 16
// speedup vs baseline: 1.2357x; 1.0518x over previous
#include <cuda_runtime.h>
#include <cuda_bf16.h>
#include <math.h>

#define HID 1024
#define IN_SIZE 228
#define COND_SIZE 100
#define N_COND 40
#define VOCAB 32000
#define NSTEPS 512
#define FEAT 1252           // HID + IN_SIZE
#define SCAN_CTAS 128
#define AUX_CTAS 168        // extra CTAs in the scan launch doing wconv+outde

// ---------------- scratch (device globals; no allocation allowed) ------------
__device__ float g_de[IN_SIZE];
__device__ float g_h0[HID];
__device__ float g_gi[2 * 3 * HID];
__device__ float g_outde[VOCAB];         // de-part + out_b
__device__ float g_hs[NSTEPS * HID];     // hidden states (GEMM A, fp32 master)
__device__ unsigned int g_cnt;           // R1 barrier: monotonic counter
__device__ volatile unsigned int g_flag; // R1 barrier: monotonic release flag
// split-bf16 operands for the tensor-core GEMM
__device__ __nv_bfloat16 g_ahi[NSTEPS * HID];
__device__ __nv_bfloat16 g_alo[NSTEPS * HID];
__device__ __nv_bfloat16 g_whi[(size_t)VOCAB * HID];
__device__ __nv_bfloat16 g_wlo[(size_t)VOCAB * HID];

// ---------------- f32x2 helpers ----------------------------------------------
__device__ __forceinline__ unsigned long long pk2(float lo, float hi) {
    unsigned long long r;
    asm("mov.b64 %0, {%1,%2};" : "=l"(r) : "f"(lo), "f"(hi));
    return r;
}
__device__ __forceinline__ unsigned long long fma2(unsigned long long a,
                                                   unsigned long long b,
                                                   unsigned long long c) {
    unsigned long long d;
    asm("fma.rn.f32x2 %0, %1, %2, %3;" : "=l"(d) : "l"(a), "l"(b), "l"(c));
    return d;
}
__device__ __forceinline__ float2 upk2(unsigned long long v) {
    float2 f;
    asm("mov.b64 {%0,%1}, %2;" : "=f"(f.x), "=f"(f.y) : "l"(v));
    return f;
}

// ---------------- prep: de, h0, barrier reset --------------------------------
__global__ void prep_kernel(const float* __restrict__ z,
                            const float* __restrict__ cond,
                            const float* __restrict__ i2h_W,
                            const float* __restrict__ i2h_b,
                            const float* __restrict__ c2h_W,
                            const float* __restrict__ c2h_b) {
    __shared__ float sde[IN_SIZE];
    int tid = threadIdx.x;
    if (tid < 128) sde[tid] = z[tid];
    if (tid < COND_SIZE) {
        float acc = c2h_b[tid];
#pragma unroll
        for (int k = 0; k < N_COND; k++) acc += cond[k] * c2h_W[tid * N_COND + k];
        sde[128 + tid] = acc;
    }
    if (tid == 0) { g_cnt = 0; g_flag = 0; }
    __syncthreads();
    if (tid < IN_SIZE) g_de[tid] = sde[tid];
    for (int r = tid; r < HID; r += blockDim.x) {
        float acc = i2h_b[r];
        const float* w = i2h_W + (size_t)r * IN_SIZE;
#pragma unroll 4
        for (int k = 0; k < IN_SIZE; k++) acc += sde[k] * w[k];
        g_h0[r] = acc;
    }
}

// ---------------- gi: the 2 distinct input-gate rows -------------------------
__global__ void gi_kernel(const float* __restrict__ embed_W,
                          const float* __restrict__ W_ih,
                          const float* __restrict__ b_ih,
                          const float* __restrict__ b_hh) {
    __shared__ float xs[2][FEAT];
    int tid = threadIdx.x;
    for (int i = tid; i < HID; i += blockDim.x) {
        xs[0][i] = fmaxf(embed_W[1 * HID + i], 0.f);  // SOS = 1
        xs[1][i] = fmaxf(embed_W[2 * HID + i], 0.f);  // UNK = 2
    }
    for (int i = tid; i < IN_SIZE; i += blockDim.x) {
        float d = g_de[i];
        xs[0][HID + i] = d;
        xs[1][HID + i] = d;
    }
    __syncthreads();
    int lane = tid & 31;
    int warp = (blockIdx.x * blockDim.x + tid) >> 5;
    int nwarp = (gridDim.x * blockDim.x) >> 5;
    for (int task = warp; task < 2 * 3 * HID; task += nwarp) {
        int v = task >= 3 * HID;
        int row = task - v * 3 * HID;
        const float* w = W_ih + (size_t)row * FEAT;
        const float* x = xs[v];
        float acc = 0.f;
        for (int k = lane; k < FEAT; k += 32) acc += w[k] * x[k];
#pragma unroll
        for (int o = 16; o > 0; o >>= 1) acc += __shfl_xor_sync(0xffffffffu, acc, o);
        if (lane == 0) {
            float val = acc + b_ih[row];
            if (row < 2 * HID) val += b_hh[row];
            g_gi[task] = val;
        }
    }
}

// ---------------- A conversion: g_hs -> hi/lo bf16 ---------------------------
__global__ void aconv_kernel() {
    size_t i8 = (size_t)blockIdx.x * blockDim.x + threadIdx.x;
    if (i8 >= (size_t)NSTEPS * HID / 8) return;
    const float4* src = (const float4*)(g_hs + i8 * 8);
    float4 v0 = src[0], v1 = src[1];
    float v[8] = { v0.x, v0.y, v0.z, v0.w, v1.x, v1.y, v1.z, v1.w };
    unsigned hu[4], lu[4];
#pragma unroll
    for (int p = 0; p < 4; p++) {
        __nv_bfloat16 h0 = __float2bfloat16(v[2 * p]);
        __nv_bfloat16 h1 = __float2bfloat16(v[2 * p + 1]);
        __nv_bfloat16 l0 = __float2bfloat16(v[2 * p] - __bfloat162float(h0));
        __nv_bfloat16 l1 = __float2bfloat16(v[2 * p + 1] - __bfloat162float(h1));
        hu[p] = (unsigned)__bfloat16_as_ushort(h0) | ((unsigned)__bfloat16_as_ushort(h1) << 16);
        lu[p] = (unsigned)__bfloat16_as_ushort(l0) | ((unsigned)__bfloat16_as_ushort(l1) << 16);
    }
    *(uint4*)(g_ahi + i8 * 8) = make_uint4(hu[0], hu[1], hu[2], hu[3]);
    *(uint4*)(g_alo + i8 * 8) = make_uint4(lu[0], lu[1], lu[2], lu[3]);
}

// ---------------- scan + aux: blocks 0-127 scan (R8-EXACT, frozen), ----------
// blocks 128+ do wconv + outde grid-stride, overlapped behind the scan.
__global__ void __launch_bounds__(256) scan_kernel(const float* __restrict__ W_hh,
                                                   const float* __restrict__ b_hh,
                                                   const float* __restrict__ out_W,
                                                   const float* __restrict__ out_b) {
    int tid = threadIdx.x;
    int bid = blockIdx.x;

    if (bid >= SCAN_CTAS) {
        // ---------------- aux path: wconv then outde ------------------------
        int gt = (bid - SCAN_CTAS) * 256 + tid;
        int nthr = AUX_CTAS * 256;
        for (size_t i8 = gt; i8 < (size_t)VOCAB * HID / 8; i8 += nthr) {
            int r = (int)(i8 >> 7);
            int c8 = (int)(i8 & 127);
            const float4* src = (const float4*)(out_W + (size_t)r * FEAT + c8 * 8);
            float4 v0 = src[0], v1 = src[1];
            float v[8] = { v0.x, v0.y, v0.z, v0.w, v1.x, v1.y, v1.z, v1.w };
            unsigned hu[4], lu[4];
#pragma unroll
            for (int p = 0; p < 4; p++) {
                __nv_bfloat16 h0 = __float2bfloat16(v[2 * p]);
                __nv_bfloat16 h1 = __float2bfloat16(v[2 * p + 1]);
                __nv_bfloat16 l0 = __float2bfloat16(v[2 * p] - __bfloat162float(h0));
                __nv_bfloat16 l1 = __float2bfloat16(v[2 * p + 1] - __bfloat162float(h1));
                hu[p] = (unsigned)__bfloat16_as_ushort(h0) | ((unsigned)__bfloat16_as_ushort(h1) << 16);
                lu[p] = (unsigned)__bfloat16_as_ushort(l0) | ((unsigned)__bfloat16_as_ushort(l1) << 16);
            }
            *(uint4*)(g_whi + i8 * 8) = make_uint4(hu[0], hu[1], hu[2], hu[3]);
            *(uint4*)(g_wlo + i8 * 8) = make_uint4(lu[0], lu[1], lu[2], lu[3]);
        }
        for (int v = gt; v < VOCAB; v += nthr) {
            const float* w = out_W + (size_t)v * FEAT + HID;
            float acc = out_b[v];
#pragma unroll 4
            for (int k = 0; k < IN_SIZE; k++) acc += g_de[k] * w[k];
            g_outde[v] = acc;
        }
        return;
    }

    // ---------------- scan path (R8-EXACT; FROZEN) --------------------------
    __shared__ float sh[HID];
    int lane = tid & 31;
    int w = tid >> 5;
    int j = bid * 8 + w;

    const float* Wr = W_hh + (size_t)j * HID;
    const float* Wu = W_hh + (size_t)(HID + j) * HID;
    const float* Wn = W_hh + (size_t)(2 * HID + j) * HID;

    unsigned long long wr2[16], wu2[16], wn2[16];
#pragma unroll
    for (int k = 0; k < 16; k++) {
        float2 a = *(const float2*)(Wr + 64 * k + 2 * lane); wr2[k] = pk2(a.x, a.y);
        float2 b = *(const float2*)(Wu + 64 * k + 2 * lane); wu2[k] = pk2(b.x, b.y);
        float2 c = *(const float2*)(Wn + 64 * k + 2 * lane); wn2[k] = pk2(c.x, c.y);
    }
    float gi_r0 = g_gi[j],           gi_u0 = g_gi[HID + j],     gi_n0 = g_gi[2 * HID + j];
    float gi_r1 = g_gi[3 * HID + j], gi_u1 = g_gi[4 * HID + j], gi_n1 = g_gi[5 * HID + j];
    float bhn = b_hh[2 * HID + j];

    for (int t = 0; t < NSTEPS; t++) {
        const float4* src = (const float4*)((t == 0) ? g_h0 : (g_hs + (size_t)(t - 1) * HID));
        ((float4*)sh)[tid] = __ldcg(src + tid);
        __syncthreads();

        unsigned long long ar2 = 0ull, au2 = 0ull, an2 = 0ull;
#pragma unroll
        for (int k = 0; k < 16; k++) {
            float2 h2 = *(const float2*)&sh[64 * k + 2 * lane];
            unsigned long long hp = pk2(h2.x, h2.y);
            ar2 = fma2(wr2[k], hp, ar2);
            au2 = fma2(wu2[k], hp, au2);
            an2 = fma2(wn2[k], hp, an2);
        }
        float2 fr = upk2(ar2), fu = upk2(au2), fn = upk2(an2);
        float ar = fr.x + fr.y, au = fu.x + fu.y, an = fn.x + fn.y;
#pragma unroll
        for (int o = 16; o > 0; o >>= 1) {
            ar += __shfl_xor_sync(0xffffffffu, ar, o);
            au += __shfl_xor_sync(0xffffffffu, au, o);
            an += __shfl_xor_sync(0xffffffffu, an, o);
        }
        if (lane == 0) {
            float gr = (t == 0) ? gi_r0 : gi_r1;
            float gu = (t == 0) ? gi_u0 : gi_u1;
            float gn = (t == 0) ? gi_n0 : gi_n1;
            float r = 1.f / (1.f + __expf(-(gr + ar)));
            float u = 1.f / (1.f + __expf(-(gu + au)));
            float narg = gn + r * (an + bhn);
            float n = 1.f - 2.f / (__expf(2.f * narg) + 1.f);
            float hnew = (1.f - u) * n + u * sh[j];
            __stcg(g_hs + (size_t)t * HID + j, hnew);
        }
        __threadfence();
        __syncthreads();
        if (tid == 0) {
            unsigned target = (unsigned)SCAN_CTAS * (unsigned)(t + 1);
            unsigned old = atomicAdd(&g_cnt, 1u);
            if (old == target - 1u) {
                g_flag = (unsigned)(t + 1);
            } else {
                while (g_flag < (unsigned)(t + 1)) {}
            }
            __threadfence();
        }
        __syncthreads();
    }
}

// ---------------- tensor-core GEMM: cp.async 2-stage + ldmatrix, occ=2 -------
// C[512,32000] = (Ahi+Alo)(Whi+Wlo)^T + outde, dropping lo*lo.
// CTA 128x128xK32; 8 warps as 2(M)x4(N); warp tile 64x32.
#define MMA_OP(d, a, b)                                                        \
    asm("mma.sync.aligned.m16n8k16.row.col.f32.bf16.bf16.f32 "                 \
        "{%0,%1,%2,%3}, {%4,%5,%6,%7}, {%8,%9}, {%0,%1,%2,%3};"                \
        : "+f"(d[0]), "+f"(d[1]), "+f"(d[2]), "+f"(d[3])                        \
        : "r"(a[0]), "r"(a[1]), "r"(a[2]), "r"(a[3]), "r"(b[0]), "r"(b[1]))

#define LDSM_X4(r, addr)                                                       \
    asm volatile("ldmatrix.sync.aligned.m8n8.x4.shared.b16 {%0,%1,%2,%3}, [%4];" \
                 : "=r"((r)[0]), "=r"((r)[1]), "=r"((r)[2]), "=r"((r)[3])       \
                 : "r"(addr))

#define CP_ASYNC16(smem_u32v, gptr)                                            \
    asm volatile("cp.async.cg.shared.global [%0], [%1], 16;"                   \
                 :: "r"(smem_u32v), "l"(gptr))
#define CP_COMMIT()  asm volatile("cp.async.commit_group;")
#define CP_WAIT(n)   asm volatile("cp.async.wait_group %0;" :: "n"(n))

#define KPAD 40
#define TILE_H (128 * KPAD)          // halves per tile
#define STAGE_H (4 * TILE_H)         // Ahi, Alo, Bhi, Blo
#define GEMM_SMEM_BYTES (2 * STAGE_H * 2)

__device__ __forceinline__ unsigned smem_u32(const void* p) {
    return (unsigned)__cvta_generic_to_shared(p);
}

__global__ void __launch_bounds__(256, 2) mma_gemm_kernel(float* __restrict__ out) {
    extern __shared__ __nv_bfloat16 smem[];
    int tid = threadIdx.x;
    int lane = tid & 31, wid = tid >> 5;
    int wm = wid & 1, wn = wid >> 1;
    int g = lane >> 2, tig = lane & 3;
    int tn = blockIdx.x * 128, tm = blockIdx.y * 128;
    int trow = lane & 7, tsel = lane >> 3;

    float acc[4][4][4];
#pragma unroll
    for (int mi = 0; mi < 4; mi++)
#pragma unroll
        for (int ni = 0; ni < 4; ni++)
#pragma unroll
            for (int p = 0; p < 4; p++) acc[mi][ni][p] = 0.f;

    int j0 = tid * 2;
    int r0_ = j0 >> 2, q0_ = j0 & 3;
    int r1_ = (j0 + 1) >> 2, q1_ = (j0 + 1) & 3;

    auto prefetch = [&](int k0, int st) {
        __nv_bfloat16* base = smem + st * STAGE_H;
        const __nv_bfloat16* srcs[4] = {
            g_ahi + (size_t)(tm + 0) * HID, g_alo + (size_t)(tm + 0) * HID,
            g_whi + (size_t)(tn + 0) * HID, g_wlo + (size_t)(tn + 0) * HID };
#pragma unroll
        for (int w4 = 0; w4 < 4; w4++) {
            const __nv_bfloat16* s = srcs[w4] + k0;
            __nv_bfloat16* d = base + w4 * TILE_H;
            CP_ASYNC16(smem_u32(d + r0_ * KPAD + q0_ * 8), s + (size_t)r0_ * HID + q0_ * 8);
            CP_ASYNC16(smem_u32(d + r1_ * KPAD + q1_ * 8), s + (size_t)r1_ * HID + q1_ * 8);
        }
    };

    prefetch(0, 0);
    CP_COMMIT();

    for (int it = 0; it < 32; it++) {
        int cur = it & 1;
        if (it < 31) { prefetch((it + 1) * 32, cur ^ 1); CP_COMMIT(); }
        if (it < 31) { CP_WAIT(1); } else { CP_WAIT(0); }
        __syncthreads();

        __nv_bfloat16* Ah = smem + cur * STAGE_H;
        __nv_bfloat16* Al = Ah + TILE_H;
        __nv_bfloat16* Bh = Al + TILE_H;
        __nv_bfloat16* Bl = Bh + TILE_H;

#pragma unroll
        for (int ks = 0; ks < 2; ks++) {
            int kk0 = ks * 16;
            unsigned bh[4][2], bl[4][2];
#pragma unroll
            for (int p = 0; p < 2; p++) {
                int rn0 = wn * 32 + p * 16;
                int brow = rn0 + (tsel >> 1) * 8 + trow;
                int bk = kk0 + (tsel & 1) * 8;
                unsigned rh[4], rl[4];
                LDSM_X4(rh, smem_u32(Bh + brow * KPAD + bk));
                LDSM_X4(rl, smem_u32(Bl + brow * KPAD + bk));
                bh[2 * p][0] = rh[0]; bh[2 * p][1] = rh[1];
                bh[2 * p + 1][0] = rh[2]; bh[2 * p + 1][1] = rh[3];
                bl[2 * p][0] = rl[0]; bl[2 * p][1] = rl[1];
                bl[2 * p + 1][0] = rl[2]; bl[2 * p + 1][1] = rl[3];
            }
#pragma unroll
            for (int mi = 0; mi < 4; mi++) {
                int rm0 = wm * 64 + mi * 16;
                int arow = rm0 + (tsel & 1) * 8 + trow;
                int ak = kk0 + (tsel >> 1) * 8;
                unsigned ah[4], al[4];
                LDSM_X4(ah, smem_u32(Ah + arow * KPAD + ak));
                LDSM_X4(al, smem_u32(Al + arow * KPAD + ak));
#pragma unroll
                for (int ni = 0; ni < 4; ni++) {
                    MMA_OP(acc[mi][ni], ah, bh[ni]);
                    MMA_OP(acc[mi][ni], ah, bl[ni]);
                    MMA_OP(acc[mi][ni], al, bh[ni]);
                }
            }
        }
        __syncthreads();
    }

#pragma unroll
    for (int mi = 0; mi < 4; mi++) {
#pragma unroll
        for (int ni = 0; ni < 4; ni++) {
            int row = tm + wm * 64 + mi * 16 + g;
            int col = tn + wn * 32 + ni * 8 + 2 * tig;
            float o0 = g_outde[col], o1 = g_outde[col + 1];
            float2 r0 = { acc[mi][ni][0] + o0, acc[mi][ni][1] + o1 };
            float2 r1 = { acc[mi][ni][2] + o0, acc[mi][ni][3] + o1 };
            *(float2*)(out + (size_t)row * VOCAB + col) = r0;
            *(float2*)(out + (size_t)(row + 8) * VOCAB + col) = r1;
        }
    }
}

// ---------------- entry ------------------------------------------------------
extern "C" void kernel_launch(void* const* d_in, const int* in_sizes, int n_in,
                              void* d_out, int out_size) {
    const float* z      = (const float*)d_in[0];
    const float* cond   = (const float*)d_in[1];
    // d_in[2] = inputs (unused: word_dropout=1.0), d_in[3] = temperature (unused)
    const float* embedW = (const float*)d_in[4];
    const float* W_ih   = (const float*)d_in[5];
    const float* W_hh   = (const float*)d_in[6];
    const float* b_ih   = (const float*)d_in[7];
    const float* b_hh   = (const float*)d_in[8];
    const float* i2h_W  = (const float*)d_in[9];
    const float* i2h_b  = (const float*)d_in[10];
    const float* c2h_W  = (const float*)d_in[11];
    const float* c2h_b  = (const float*)d_in[12];
    const float* out_W  = (const float*)d_in[13];
    const float* out_b  = (const float*)d_in[14];
    float* out = (float*)d_out;

    cudaFuncSetAttribute(mma_gemm_kernel,
                         cudaFuncAttributeMaxDynamicSharedMemorySize,
                         GEMM_SMEM_BYTES);

    prep_kernel<<<1, 256>>>(z, cond, i2h_W, i2h_b, c2h_W, c2h_b);
    gi_kernel<<<96, 256>>>(embedW, W_ih, b_ih, b_hh);
    // scan (blocks 0-127) + overlapped wconv/outde (blocks 128+)
    scan_kernel<<<SCAN_CTAS + AUX_CTAS, 256>>>(W_hh, b_hh, out_W, out_b);
    aconv_kernel<<<(NSTEPS * (HID / 8) + 255) / 256, 256>>>();
    mma_gemm_kernel<<<dim3(VOCAB / 128, NSTEPS / 128), 256, GEMM_SMEM_BYTES>>>(out);
}